// round 4
// baseline (speedup 1.0000x reference)
#include <cuda_runtime.h>
#include <cuda_bf16.h>
#include <cuda_fp8.h>
#include <stdint.h>

#define ATOMS   4096
#define DMODEL  16384
#define BATCH   32
#define ITERS   10
#define TEMP    0.001f

#define KCHUNKS 8
#define KCHUNK  (DMODEL / KCHUNKS)   // 2048
#define ATILE   64                   // atoms per CTA
#define NTILES  (ATOMS / ATILE)      // 64
#define KB      128                  // fp8 k elems per pipeline stage
#define NSTAGE  3
#define NSTEPS  (KCHUNK / KB)        // 16
#define MAXC    64
#define WINDOW  0.75f                // candidate window (true-score units)

#define DSCALE  8192.0f              // dict fp8 scale
#define RSCALE  32.0f                // residual fp8 scale
#define INV_S   (1.0f / (DSCALE * RSCALE))

#define SROW    (KB + 16)            // smem row stride in bytes (144)

#define NRES (BATCH * DMODEL)        // 524288

// ---------------- persistent scratch (device globals; no allocs) -----------
__device__ uint8_t g_dict_f8[(size_t)ATOMS * DMODEL];              // 64 MB
__device__ float   g_resid[(size_t)BATCH * DMODEL];                // 2 MB
__device__ uint8_t g_resid_f8[(size_t)BATCH * DMODEL];             // 0.5 MB
__device__ float   g_part[(size_t)KCHUNKS * BATCH * ATOMS];        // 4 MB
__device__ int     g_cand[BATCH * MAXC];
__device__ float   g_w[BATCH * MAXC];
__device__ int     g_n[BATCH];
__device__ float   g_lpart[512];

// ---------------- PTX helpers ----------------------------------------------
__device__ __forceinline__ uint32_t smem_u32(const void* p) {
    return (uint32_t)__cvta_generic_to_shared(p);
}
__device__ __forceinline__ void cpa16(uint32_t s, const void* g) {
    asm volatile("cp.async.cg.shared.global [%0], [%1], 16;\n" :: "r"(s), "l"(g));
}
__device__ __forceinline__ void cpa_commit() {
    asm volatile("cp.async.commit_group;\n");
}
__device__ __forceinline__ void cpa_wait2() {
    asm volatile("cp.async.wait_group 2;\n");
}
__device__ __forceinline__ void ldsm_x4(uint32_t* r, uint32_t addr) {
    asm volatile("ldmatrix.sync.aligned.m8n8.x4.shared.b16 {%0,%1,%2,%3}, [%4];\n"
        : "=r"(r[0]), "=r"(r[1]), "=r"(r[2]), "=r"(r[3]) : "r"(addr));
}
__device__ __forceinline__ void ldsm_x2(uint32_t* r, uint32_t addr) {
    asm volatile("ldmatrix.sync.aligned.m8n8.x2.shared.b16 {%0,%1}, [%2];\n"
        : "=r"(r[0]), "=r"(r[1]) : "r"(addr));
}
// fp8 e4m3 MMA: D(16x8,f32) += A(16x32) * B(32x8)
__device__ __forceinline__ void mma16832(float* c, const uint32_t* a, const uint32_t* b) {
    asm volatile(
        "mma.sync.aligned.m16n8k32.row.col.f32.e4m3.e4m3.f32 "
        "{%0,%1,%2,%3}, {%4,%5,%6,%7}, {%8,%9}, {%0,%1,%2,%3};\n"
        : "+f"(c[0]), "+f"(c[1]), "+f"(c[2]), "+f"(c[3])
        : "r"(a[0]), "r"(a[1]), "r"(a[2]), "r"(a[3]), "r"(b[0]), "r"(b[1]));
}
__device__ __forceinline__ uint32_t f8x4(float x, float y, float z, float w) {
    __nv_fp8x4_e4m3 p(make_float4(x, y, z, w));
    return *(uint32_t*)&p;
}

// ---------------- kernels ---------------------------------------------------

// dict fp32 -> scaled fp8 (once per launch). 4 elems/thread.
__global__ void k_convert_dict(const float* __restrict__ dict) {
    size_t i = ((size_t)blockIdx.x * blockDim.x + threadIdx.x) * 4;
    float4 v = *(const float4*)(dict + i);
    *(uint32_t*)(g_dict_f8 + i) =
        f8x4(v.x * DSCALE, v.y * DSCALE, v.z * DSCALE, v.w * DSCALE);
}

// residual init = x (fp32 + scaled fp8 mirror).
__global__ void k_init(const float* __restrict__ x) {
    size_t i = ((size_t)blockIdx.x * blockDim.x + threadIdx.x) * 4;
    float4 v = *(const float4*)(x + i);
    *(float4*)(g_resid + i) = v;
    *(uint32_t*)(g_resid_f8 + i) =
        f8x4(v.x * RSCALE, v.y * RSCALE, v.z * RSCALE, v.w * RSCALE);
}

// Approx scores (fp8 tensor cores), 3-stage cp.async pipeline.
// grid (NTILES, KCHUNKS), 256 threads (8 warps x 8 atoms).
__global__ void __launch_bounds__(256) k_scores() {
    __shared__ uint8_t sD[NSTAGE][ATILE][SROW];   // 3 x 64 x 144
    __shared__ uint8_t sR[NSTAGE][BATCH][SROW];   // 3 x 32 x 144

    const int t = threadIdx.x;
    const int lane = t & 31, warp = t >> 5;
    const int atomBase = blockIdx.x * ATILE;
    const int kBase = blockIdx.y * KCHUNK;

    float c0[4] = {0.f, 0.f, 0.f, 0.f};
    float c1[4] = {0.f, 0.f, 0.f, 0.f};

    // fragment addressing (fp8-as-b16 ldmatrix trick)
    const int arow = lane & 15;
    const int acolsel = (lane & 16) ? 16 : 0;     // bytes
    const int brow = warp * 8 + (lane & 7);
    const int bcolsel = (lane & 8) ? 16 : 0;      // bytes

    // per-thread cp.async coordinates: dict 2x16B, resid 1x16B per stage
    const int dr0 = t >> 3, ds = t & 7;           // dict rows 0..31
    const int dr1 = dr0 + 32;                     // dict rows 32..63
    const int rr = t >> 3, rs = t & 7;            // resid rows 0..31

    auto load_stage = [&](int buf, int kb) {
        const size_t gk = (size_t)(kBase + kb);
        cpa16(smem_u32(&sD[buf][dr0][ds * 16]),
              &g_dict_f8[(size_t)(atomBase + dr0) * DMODEL + gk + ds * 16]);
        cpa16(smem_u32(&sD[buf][dr1][ds * 16]),
              &g_dict_f8[(size_t)(atomBase + dr1) * DMODEL + gk + ds * 16]);
        cpa16(smem_u32(&sR[buf][rr][rs * 16]),
              &g_resid_f8[(size_t)rr * DMODEL + gk + rs * 16]);
        cpa_commit();
    };

    load_stage(0, 0);
    load_stage(1, KB);

    for (int s = 0; s < NSTEPS; s++) {
        if (s + NSTAGE - 1 < NSTEPS) load_stage((s + NSTAGE - 1) % NSTAGE, (s + NSTAGE - 1) * KB);
        else cpa_commit();
        cpa_wait2();
        __syncthreads();

        const int b = s % NSTAGE;
        #pragma unroll
        for (int ks = 0; ks < KB / 32; ks++) {
            uint32_t a0[4], a1[4], bb[2];
            const int col = ks * 32;
            ldsm_x4(a0, smem_u32(&sR[b][arow][col + acolsel]));
            ldsm_x4(a1, smem_u32(&sR[b][16 + arow][col + acolsel]));
            ldsm_x2(bb, smem_u32(&sD[b][brow][col + bcolsel]));
            mma16832(c0, a0, bb);
            mma16832(c1, a1, bb);
        }
        __syncthreads();
    }

    const int gr = lane >> 2;
    const int acol = atomBase + warp * 8 + (lane & 3) * 2;
    float* P = g_part + (size_t)blockIdx.y * BATCH * ATOMS;
    P[(size_t)(gr + 0)  * ATOMS + acol]     = c0[0];
    P[(size_t)(gr + 0)  * ATOMS + acol + 1] = c0[1];
    P[(size_t)(gr + 8)  * ATOMS + acol]     = c0[2];
    P[(size_t)(gr + 8)  * ATOMS + acol + 1] = c0[3];
    P[(size_t)(gr + 16) * ATOMS + acol]     = c1[0];
    P[(size_t)(gr + 16) * ATOMS + acol + 1] = c1[1];
    P[(size_t)(gr + 24) * ATOMS + acol]     = c1[2];
    P[(size_t)(gr + 24) * ATOMS + acol + 1] = c1[3];
}

// Fused: reduce partials (smem), max, candidate select, warp-parallel exact
// fp32 rescore, softmax. grid 32 x 1024.
__global__ void __launch_bounds__(1024) k_select(const float* __restrict__ dict) {
    __shared__ float s_scores[ATOMS];   // 16 KB
    __shared__ float sred[32];
    __shared__ float s_thr;
    __shared__ int   s_cnt, s_n;
    __shared__ int   s_idx[MAXC];
    __shared__ float s_ex[MAXC];

    const int r = blockIdx.x, t = threadIdx.x;
    const int lane = t & 31, w = t >> 5;

    if (t == 0) s_cnt = 0;

    // reduce 8 K-chunk partials (L2-hot), scale to true units, track max
    float lmax = -1e30f;
    {
        const int a4 = t * 4;                      // 1024*4 = 4096
        float4 s = make_float4(0.f, 0.f, 0.f, 0.f);
        #pragma unroll
        for (int c = 0; c < KCHUNKS; c++) {
            const float4 p = *(const float4*)&g_part[((size_t)c * BATCH + r) * ATOMS + a4];
            s.x += p.x; s.y += p.y; s.z += p.z; s.w += p.w;
        }
        s.x *= INV_S; s.y *= INV_S; s.z *= INV_S; s.w *= INV_S;
        *(float4*)&s_scores[a4] = s;
        lmax = fmaxf(fmaxf(s.x, s.y), fmaxf(s.z, s.w));
    }
    #pragma unroll
    for (int o = 16; o > 0; o >>= 1) lmax = fmaxf(lmax, __shfl_xor_sync(0xffffffffu, lmax, o));
    if (lane == 0) sred[w] = lmax;
    __syncthreads();
    if (t == 0) {
        float mm = -1e30f;
        #pragma unroll
        for (int i = 0; i < 32; i++) mm = fmaxf(mm, sred[i]);
        s_thr = mm - WINDOW;
    }
    __syncthreads();
    const float thr = s_thr;

    #pragma unroll
    for (int i = 0; i < 4; i++) {
        const int a = t * 4 + i;
        if (s_scores[a] > thr) {
            int p = atomicAdd(&s_cnt, 1);
            if (p < MAXC) s_idx[p] = a;
        }
    }
    __syncthreads();
    if (t == 0) {
        int n = min(s_cnt, MAXC);
        for (int i = 1; i < n; i++) {
            int v = s_idx[i], j = i - 1;
            while (j >= 0 && s_idx[j] > v) { s_idx[j + 1] = s_idx[j]; j--; }
            s_idx[j + 1] = v;
        }
        s_n = n;
    }
    __syncthreads();
    const int n = s_n;

    // exact fp32 rescore: one warp per candidate
    const float* R = g_resid + (size_t)r * DMODEL;
    for (int j = w; j < n; j += 32) {
        const float* D = dict + (size_t)s_idx[j] * DMODEL;
        float acc = 0.f;
        for (int d = lane * 4; d < DMODEL; d += 128) {
            const float4 rv = *(const float4*)(R + d);
            const float4 dv = *(const float4*)(D + d);
            acc += rv.x * dv.x + rv.y * dv.y + rv.z * dv.z + rv.w * dv.w;
        }
        #pragma unroll
        for (int o = 16; o > 0; o >>= 1) acc += __shfl_xor_sync(0xffffffffu, acc, o);
        if (lane == 0) s_ex[j] = acc;
    }
    __syncthreads();

    if (t == 0) {
        float em = -1e30f;
        for (int j = 0; j < n; j++) em = fmaxf(em, s_ex[j]);
        float den = 0.f;
        float wv[MAXC];
        for (int j = 0; j < n; j++) { wv[j] = expf((s_ex[j] - em) / TEMP); den += wv[j]; }
        const float inv = 1.f / den;
        for (int j = 0; j < n; j++) {
            g_w[r * MAXC + j] = wv[j] * inv;
            g_cand[r * MAXC + j] = s_idx[j];
        }
        g_n[r] = n;
    }
}

// Sparse residual update + fp8 mirror. grid (16, 32) x 256, float4 per thread.
__global__ void __launch_bounds__(256) k_apply(const float* __restrict__ dict) {
    const int cb = blockIdx.x, r = blockIdx.y, t = threadIdx.x;
    const int n = g_n[r];
    const int col = cb * 1024 + t * 4;
    const size_t base = (size_t)r * DMODEL + col;

    float4 v = *(const float4*)(g_resid + base);
    for (int j = 0; j < n; j++) {
        const float wj = g_w[r * MAXC + j];
        const float4 dv = *(const float4*)(dict + (size_t)g_cand[r * MAXC + j] * DMODEL + col);
        v.x -= wj * dv.x; v.y -= wj * dv.y; v.z -= wj * dv.z; v.w -= wj * dv.w;
    }
    *(float4*)(g_resid + base) = v;
    *(uint32_t*)(g_resid_f8 + base) =
        f8x4(v.x * RSCALE, v.y * RSCALE, v.z * RSCALE, v.w * RSCALE);
}

// loss partials: block b sums its contiguous 1024-elem slab
__global__ void k_losspart() {
    __shared__ float s[256];
    const int b = blockIdx.x, t = threadIdx.x;
    const size_t base = (size_t)b * 1024;
    float acc = 0.f;
    for (int i = t; i < 1024; i += 256) { float v = g_resid[base + i]; acc += v * v; }
    s[t] = acc; __syncthreads();
    for (int o = 128; o > 0; o >>= 1) { if (t < o) s[t] += s[t + o]; __syncthreads(); }
    if (t == 0) g_lpart[b] = s[0];
}

__global__ void k_finalize(float* out, int out_size) {
    __shared__ float s[512];
    const int t = threadIdx.x;
    s[t] = g_lpart[t]; __syncthreads();
    for (int o = 256; o > 0; o >>= 1) { if (t < o) s[t] += s[t + o]; __syncthreads(); }
    if (t == 0 && out_size > NRES) out[0] = s[0] / (float)NRES;
}

__global__ void k_copy(float* out, int out_size) {
    const int off = (out_size > NRES) ? 1 : 0;
    size_t i = (size_t)blockIdx.x * blockDim.x + threadIdx.x;
    if (i < (size_t)NRES) out[off + i] = g_resid[i];
}

// ---------------- launch ----------------------------------------------------
extern "C" void kernel_launch(void* const* d_in, const int* in_sizes, int n_in,
                              void* d_out, int out_size) {
    const float* x = nullptr;
    const float* dict = nullptr;
    for (int i = 0; i < n_in; i++) {
        if (in_sizes[i] == NRES) x = (const float*)d_in[i];
        else if (in_sizes[i] == ATOMS * DMODEL) dict = (const float*)d_in[i];
    }
    float* out = (float*)d_out;

    k_convert_dict<<<65536, 256>>>(dict);
    k_init<<<512, 256>>>(x);

    for (int it = 0; it < ITERS; it++) {
        k_scores<<<dim3(NTILES, KCHUNKS), 256>>>();
        k_select<<<BATCH, 1024>>>(dict);
        k_apply<<<dim3(16, BATCH), 256>>>(dict);
    }

    k_losspart<<<512, 256>>>();
    k_finalize<<<1, 512>>>(out, out_size);
    k_copy<<<2048, 256>>>(out, out_size);
}

// round 5
// speedup vs baseline: 2.0754x; 2.0754x over previous
#include <cuda_runtime.h>
#include <cuda_bf16.h>
#include <cuda_fp8.h>
#include <stdint.h>

#define ATOMS   4096
#define DMODEL  16384
#define BATCH   32
#define ITERS   10
#define TEMP    0.001f

#define KCHUNKS 8
#define KCHUNK  (DMODEL / KCHUNKS)   // 2048
#define ATILE   64                   // atoms per CTA
#define NTILES  (ATOMS / ATILE)      // 64
#define KB      128                  // fp8 k elems per pipeline stage
#define NSTAGE  3
#define NSTEPS  (KCHUNK / KB)        // 16
#define MAXC    64
#define WINDOW  0.40f                // candidate window (6.2 sigma of fp8 noise)

#define DSCALE  8192.0f              // dict fp8 scale
#define RSCALE  32.0f                // residual fp8 scale
#define INV_S   (1.0f / (DSCALE * RSCALE))

#define SROW    (KB + 16)            // smem row stride in bytes (144)

#define NRES (BATCH * DMODEL)        // 524288

// ---------------- persistent scratch (device globals; no allocs) -----------
__device__ uint8_t g_dict_f8[(size_t)ATOMS * DMODEL];              // 64 MB
__device__ float   g_resid[(size_t)BATCH * DMODEL];                // 2 MB
__device__ uint8_t g_resid_f8[(size_t)BATCH * DMODEL];             // 0.5 MB
__device__ float   g_part[(size_t)KCHUNKS * BATCH * ATOMS];        // 4 MB
__device__ float   g_scores[(size_t)BATCH * ATOMS];                // 512 KB
__device__ float   g_maxpart[BATCH * 8];
__device__ int     g_cand[BATCH * MAXC];
__device__ float   g_ex[BATCH * MAXC];
__device__ int     g_n[BATCH];
__device__ float   g_lpart[512];

// ---------------- PTX helpers ----------------------------------------------
__device__ __forceinline__ uint32_t smem_u32(const void* p) {
    return (uint32_t)__cvta_generic_to_shared(p);
}
__device__ __forceinline__ void cpa16(uint32_t s, const void* g) {
    asm volatile("cp.async.cg.shared.global [%0], [%1], 16;\n" :: "r"(s), "l"(g));
}
__device__ __forceinline__ void cpa_commit() {
    asm volatile("cp.async.commit_group;\n");
}
__device__ __forceinline__ void cpa_wait2() {
    asm volatile("cp.async.wait_group 2;\n");
}
__device__ __forceinline__ void ldsm_x4(uint32_t* r, uint32_t addr) {
    asm volatile("ldmatrix.sync.aligned.m8n8.x4.shared.b16 {%0,%1,%2,%3}, [%4];\n"
        : "=r"(r[0]), "=r"(r[1]), "=r"(r[2]), "=r"(r[3]) : "r"(addr));
}
__device__ __forceinline__ void ldsm_x2(uint32_t* r, uint32_t addr) {
    asm volatile("ldmatrix.sync.aligned.m8n8.x2.shared.b16 {%0,%1}, [%2];\n"
        : "=r"(r[0]), "=r"(r[1]) : "r"(addr));
}
// fp8 e4m3 MMA: D(16x8,f32) += A(16x32) * B(32x8)
__device__ __forceinline__ void mma16832(float* c, const uint32_t* a, const uint32_t* b) {
    asm volatile(
        "mma.sync.aligned.m16n8k32.row.col.f32.e4m3.e4m3.f32 "
        "{%0,%1,%2,%3}, {%4,%5,%6,%7}, {%8,%9}, {%0,%1,%2,%3};\n"
        : "+f"(c[0]), "+f"(c[1]), "+f"(c[2]), "+f"(c[3])
        : "r"(a[0]), "r"(a[1]), "r"(a[2]), "r"(a[3]), "r"(b[0]), "r"(b[1]));
}
__device__ __forceinline__ uint32_t f8x4(float x, float y, float z, float w) {
    __nv_fp8x4_e4m3 p(make_float4(x, y, z, w));
    return *(uint32_t*)&p;
}

// ---------------- kernels ---------------------------------------------------

__global__ void k_convert_dict(const float* __restrict__ dict) {
    size_t i = ((size_t)blockIdx.x * blockDim.x + threadIdx.x) * 4;
    float4 v = *(const float4*)(dict + i);
    *(uint32_t*)(g_dict_f8 + i) =
        f8x4(v.x * DSCALE, v.y * DSCALE, v.z * DSCALE, v.w * DSCALE);
}

__global__ void k_init(const float* __restrict__ x) {
    size_t i = ((size_t)blockIdx.x * blockDim.x + threadIdx.x) * 4;
    float4 v = *(const float4*)(x + i);
    *(float4*)(g_resid + i) = v;
    *(uint32_t*)(g_resid_f8 + i) =
        f8x4(v.x * RSCALE, v.y * RSCALE, v.z * RSCALE, v.w * RSCALE);
}

// Approx scores (fp8 tensor cores), 3-stage cp.async pipeline.
// grid (NTILES, KCHUNKS), 256 threads (8 warps x 8 atoms).
__global__ void __launch_bounds__(256) k_scores() {
    __shared__ uint8_t sD[NSTAGE][ATILE][SROW];
    __shared__ uint8_t sR[NSTAGE][BATCH][SROW];

    const int t = threadIdx.x;
    const int lane = t & 31, warp = t >> 5;
    const int atomBase = blockIdx.x * ATILE;
    const int kBase = blockIdx.y * KCHUNK;

    float c0[4] = {0.f, 0.f, 0.f, 0.f};
    float c1[4] = {0.f, 0.f, 0.f, 0.f};

    const int arow = lane & 15;
    const int acolsel = (lane & 16) ? 16 : 0;     // bytes
    const int brow = warp * 8 + (lane & 7);
    const int bcolsel = (lane & 8) ? 16 : 0;      // bytes

    const int dr0 = t >> 3, ds = t & 7;
    const int dr1 = dr0 + 32;
    const int rr = t >> 3, rs = t & 7;

    auto load_stage = [&](int buf, int kb) {
        const size_t gk = (size_t)(kBase + kb);
        cpa16(smem_u32(&sD[buf][dr0][ds * 16]),
              &g_dict_f8[(size_t)(atomBase + dr0) * DMODEL + gk + ds * 16]);
        cpa16(smem_u32(&sD[buf][dr1][ds * 16]),
              &g_dict_f8[(size_t)(atomBase + dr1) * DMODEL + gk + ds * 16]);
        cpa16(smem_u32(&sR[buf][rr][rs * 16]),
              &g_resid_f8[(size_t)rr * DMODEL + gk + rs * 16]);
        cpa_commit();
    };

    load_stage(0, 0);
    load_stage(1, KB);

    for (int s = 0; s < NSTEPS; s++) {
        if (s + NSTAGE - 1 < NSTEPS) load_stage((s + NSTAGE - 1) % NSTAGE, (s + NSTAGE - 1) * KB);
        else cpa_commit();
        cpa_wait2();
        __syncthreads();

        const int b = s % NSTAGE;
        #pragma unroll
        for (int ks = 0; ks < KB / 32; ks++) {
            uint32_t a0[4], a1[4], bb[2];
            const int col = ks * 32;
            ldsm_x4(a0, smem_u32(&sR[b][arow][col + acolsel]));
            ldsm_x4(a1, smem_u32(&sR[b][16 + arow][col + acolsel]));
            ldsm_x2(bb, smem_u32(&sD[b][brow][col + bcolsel]));
            mma16832(c0, a0, bb);
            mma16832(c1, a1, bb);
        }
        __syncthreads();
    }

    const int gr = lane >> 2;
    const int acol = atomBase + warp * 8 + (lane & 3) * 2;
    float* P = g_part + (size_t)blockIdx.y * BATCH * ATOMS;
    P[(size_t)(gr + 0)  * ATOMS + acol]     = c0[0];
    P[(size_t)(gr + 0)  * ATOMS + acol + 1] = c0[1];
    P[(size_t)(gr + 8)  * ATOMS + acol]     = c0[2];
    P[(size_t)(gr + 8)  * ATOMS + acol + 1] = c0[3];
    P[(size_t)(gr + 16) * ATOMS + acol]     = c1[0];
    P[(size_t)(gr + 16) * ATOMS + acol + 1] = c1[1];
    P[(size_t)(gr + 24) * ATOMS + acol]     = c1[2];
    P[(size_t)(gr + 24) * ATOMS + acol + 1] = c1[3];
}

// Reduce K-chunk partials -> true-unit scores + per-block max. grid (8,32) x 256.
__global__ void __launch_bounds__(256) k_reduce() {
    __shared__ float sm[256];
    const int ab = blockIdx.x, r = blockIdx.y, t = threadIdx.x;
    float lmax = -1e30f;
    #pragma unroll
    for (int i = 0; i < 2; i++) {
        int a = ab * 512 + i * 256 + t;
        float s = 0.f;
        #pragma unroll
        for (int c = 0; c < KCHUNKS; c++)
            s += g_part[((size_t)c * BATCH + r) * ATOMS + a];
        s *= INV_S;
        g_scores[(size_t)r * ATOMS + a] = s;
        lmax = fmaxf(lmax, s);
    }
    sm[t] = lmax; __syncthreads();
    for (int o = 128; o > 0; o >>= 1) {
        if (t < o) sm[t] = fmaxf(sm[t], sm[t + o]);
        __syncthreads();
    }
    if (t == 0) g_maxpart[r * 8 + ab] = sm[0];
}

// Candidate selection only (L2-hot scores). grid 32 x 256.
__global__ void __launch_bounds__(256) k_sel() {
    __shared__ float s_thr;
    __shared__ int   s_cnt;
    __shared__ int   s_idx[MAXC];
    const int r = blockIdx.x, t = threadIdx.x;

    if (t == 0) {
        s_cnt = 0;
        float mm = -1e30f;
        #pragma unroll
        for (int i = 0; i < 8; i++) mm = fmaxf(mm, g_maxpart[r * 8 + i]);
        s_thr = mm - WINDOW;
    }
    __syncthreads();
    const float thr = s_thr;

    #pragma unroll
    for (int i = 0; i < 16; i++) {
        const int a = i * 256 + t;
        if (g_scores[(size_t)r * ATOMS + a] > thr) {
            int p = atomicAdd(&s_cnt, 1);
            if (p < MAXC) s_idx[p] = a;
        }
    }
    __syncthreads();
    if (t == 0) {
        int n = min(s_cnt, MAXC);
        for (int i = 1; i < n; i++) {
            int v = s_idx[i], j = i - 1;
            while (j >= 0 && s_idx[j] > v) { s_idx[j + 1] = s_idx[j]; j--; }
            s_idx[j + 1] = v;
        }
        g_n[r] = n;
        for (int i = 0; i < n; i++) g_cand[r * MAXC + i] = s_idx[i];
    }
}

// Exact fp32 rescore, candidate-parallel across chip. grid (8, 32) x 256.
// CTA (cslot, r) handles candidates j = cslot, cslot+8, ...
__global__ void __launch_bounds__(256) k_rescore(const float* __restrict__ dict) {
    __shared__ float sred[8];
    const int cslot = blockIdx.x, r = blockIdx.y, t = threadIdx.x;
    const int lane = t & 31, w = t >> 5;
    const int n = g_n[r];
    const float* R = g_resid + (size_t)r * DMODEL;

    for (int j = cslot; j < n; j += 8) {
        const float* D = dict + (size_t)g_cand[r * MAXC + j] * DMODEL;
        float acc = 0.f;
        #pragma unroll 4
        for (int d = t * 4; d < DMODEL; d += 1024) {
            const float4 rv = *(const float4*)(R + d);
            const float4 dv = *(const float4*)(D + d);
            acc += rv.x * dv.x + rv.y * dv.y + rv.z * dv.z + rv.w * dv.w;
        }
        #pragma unroll
        for (int o = 16; o > 0; o >>= 1) acc += __shfl_xor_sync(0xffffffffu, acc, o);
        if (lane == 0) sred[w] = acc;
        __syncthreads();
        if (t == 0) {
            float s = 0.f;
            #pragma unroll
            for (int i = 0; i < 8; i++) s += sred[i];
            g_ex[r * MAXC + j] = s;
        }
        __syncthreads();
    }
}

// Sparse residual update + fp8 mirror; softmax recomputed per-CTA (cheap, n small).
// grid (16, 32) x 256, float4 per thread.
__global__ void __launch_bounds__(256) k_apply(const float* __restrict__ dict) {
    __shared__ float s_w[MAXC];
    __shared__ int   s_c[MAXC];
    const int cb = blockIdx.x, r = blockIdx.y, t = threadIdx.x;
    const int n = g_n[r];

    if (t == 0) {
        float em = -1e30f;
        for (int j = 0; j < n; j++) em = fmaxf(em, g_ex[r * MAXC + j]);
        float den = 0.f;
        for (int j = 0; j < n; j++) {
            float wv = expf((g_ex[r * MAXC + j] - em) / TEMP);
            s_w[j] = wv; den += wv;
        }
        const float inv = 1.f / den;
        for (int j = 0; j < n; j++) s_w[j] *= inv;
    }
    if (t < MAXC) s_c[t] = g_cand[r * MAXC + t];
    __syncthreads();

    const int col = cb * 1024 + t * 4;
    const size_t base = (size_t)r * DMODEL + col;

    float4 v = *(const float4*)(g_resid + base);
    for (int j = 0; j < n; j++) {
        const float wj = s_w[j];
        const float4 dv = *(const float4*)(dict + (size_t)s_c[j] * DMODEL + col);
        v.x -= wj * dv.x; v.y -= wj * dv.y; v.z -= wj * dv.z; v.w -= wj * dv.w;
    }
    *(float4*)(g_resid + base) = v;
    *(uint32_t*)(g_resid_f8 + base) =
        f8x4(v.x * RSCALE, v.y * RSCALE, v.z * RSCALE, v.w * RSCALE);
}

__global__ void k_losspart() {
    __shared__ float s[256];
    const int b = blockIdx.x, t = threadIdx.x;
    const size_t base = (size_t)b * 1024;
    float acc = 0.f;
    for (int i = t; i < 1024; i += 256) { float v = g_resid[base + i]; acc += v * v; }
    s[t] = acc; __syncthreads();
    for (int o = 128; o > 0; o >>= 1) { if (t < o) s[t] += s[t + o]; __syncthreads(); }
    if (t == 0) g_lpart[b] = s[0];
}

__global__ void k_finalize(float* out, int out_size) {
    __shared__ float s[512];
    const int t = threadIdx.x;
    s[t] = g_lpart[t]; __syncthreads();
    for (int o = 256; o > 0; o >>= 1) { if (t < o) s[t] += s[t + o]; __syncthreads(); }
    if (t == 0 && out_size > NRES) out[0] = s[0] / (float)NRES;
}

__global__ void k_copy(float* out, int out_size) {
    const int off = (out_size > NRES) ? 1 : 0;
    size_t i = (size_t)blockIdx.x * blockDim.x + threadIdx.x;
    if (i < (size_t)NRES) out[off + i] = g_resid[i];
}

// ---------------- launch ----------------------------------------------------
extern "C" void kernel_launch(void* const* d_in, const int* in_sizes, int n_in,
                              void* d_out, int out_size) {
    const float* x = nullptr;
    const float* dict = nullptr;
    for (int i = 0; i < n_in; i++) {
        if (in_sizes[i] == NRES) x = (const float*)d_in[i];
        else if (in_sizes[i] == ATOMS * DMODEL) dict = (const float*)d_in[i];
    }
    float* out = (float*)d_out;

    k_convert_dict<<<65536, 256>>>(dict);
    k_init<<<512, 256>>>(x);

    for (int it = 0; it < ITERS; it++) {
        k_scores<<<dim3(NTILES, KCHUNKS), 256>>>();
        k_reduce<<<dim3(8, BATCH), 256>>>();
        k_sel<<<BATCH, 256>>>();
        k_rescore<<<dim3(8, BATCH), 256>>>(dict);
        k_apply<<<dim3(16, BATCH), 256>>>(dict);
    }

    k_losspart<<<512, 256>>>();
    k_finalize<<<1, 512>>>(out, out_size);
    k_copy<<<2048, 256>>>(out, out_size);
}